// round 10
// baseline (speedup 1.0000x reference)
#include <cuda_runtime.h>
#include <cuda_fp16.h>
#include <stdint.h>
#include <math.h>

// Problem constants
#define L_SEQ 2048
#define DM    1024
#define NH    16
#define HD    64
#define BH    32
#define NEMB  1025
#define QRP   1056
#define MROWS 4096
#define NELEM (MROWS * DM)

#define MODE_PLAIN  0
#define MODE_HSPLIT 1
#define MODE_QREL   2

// ---------------- device scratch ----------------
__device__ __align__(16) __half g_qrel[BH * L_SEQ * QRP];
__device__ __align__(16) __half g_Qf[BH * L_SEQ * HD];
__device__ __align__(16) __half g_Kf[BH * L_SEQ * HD];
__device__ __align__(16) __half g_Vf[BH * L_SEQ * HD];
__device__ __align__(16) __half g_Act[3 * NELEM];      // q,k,v activations; slot 0 reused for attn out
__device__ __align__(16) __half g_Wh[4 * DM * DM];
__device__ __align__(16) __half g_Wl[4 * DM * DM];
__device__ __align__(16) __half g_Ef[NEMB * HD];

struct GemmBatch {
    const __half* A[3];
    const float*  bias[3];
    __half*       Cf[3];
};

// ---------------- helpers ----------------
static __device__ __forceinline__ uint32_t smem_u32(const void* p) {
    uint32_t a;
    asm("{ .reg .u64 t; cvta.to.shared.u64 t, %1; cvt.u32.u64 %0, t; }" : "=r"(a) : "l"(p));
    return a;
}
static __device__ __forceinline__ uint32_t swz(uint32_t b) { return b ^ ((b >> 3) & 0x70); }

static __device__ __forceinline__ void ldmx4(uint32_t* r, uint32_t addr) {
    asm volatile("ldmatrix.sync.aligned.m8n8.x4.shared.b16 {%0,%1,%2,%3}, [%4];"
                 : "=r"(r[0]), "=r"(r[1]), "=r"(r[2]), "=r"(r[3]) : "r"(addr));
}
static __device__ __forceinline__ void ldmx4t(uint32_t* r, uint32_t addr) {
    asm volatile("ldmatrix.sync.aligned.m8n8.x4.trans.shared.b16 {%0,%1,%2,%3}, [%4];"
                 : "=r"(r[0]), "=r"(r[1]), "=r"(r[2]), "=r"(r[3]) : "r"(addr));
}
static __device__ __forceinline__ void mma_f16(float* c, const uint32_t* a, const uint32_t* b) {
    asm volatile("mma.sync.aligned.m16n8k16.row.col.f32.f16.f16.f32 "
                 "{%0,%1,%2,%3}, {%4,%5,%6,%7}, {%8,%9}, {%0,%1,%2,%3};"
                 : "+f"(c[0]), "+f"(c[1]), "+f"(c[2]), "+f"(c[3])
                 : "r"(a[0]), "r"(a[1]), "r"(a[2]), "r"(a[3]), "r"(b[0]), "r"(b[1]));
}
static __device__ __forceinline__ void cpasync16(uint32_t dst, const void* src, uint32_t ssz) {
    asm volatile("cp.async.cg.shared.global [%0], [%1], 16, %2;"
                 :: "r"(dst), "l"(src), "r"(ssz) : "memory");
}
static __device__ __forceinline__ void cp_commit() {
    asm volatile("cp.async.commit_group;" ::: "memory");
}
static __device__ __forceinline__ uint32_t packh2(float a, float b) {
    __half2 h = __floats2half2_rn(a, b);
    return *(uint32_t*)&h;
}

// ---------------- batched fp32 -> fp16 (q,k,v inputs + rel_emb) ----------------
__global__ void convert4_f16(const float* __restrict__ x0, const float* __restrict__ x1,
                             const float* __restrict__ x2, const float* __restrict__ x3)
{
    const int z = blockIdx.y;
    if (z == 3) {
        // rel_emb: NEMB*HD = 65600 elements -> 65 blocks worth
        const int n = NEMB * HD;
        int i = (blockIdx.x * blockDim.x + threadIdx.x) * 4;
        if (i >= n) return;
        float4 v = *(const float4*)(x3 + i);
        __half2* Y = (__half2*)(g_Ef + i);
        Y[0] = __floats2half2_rn(v.x, v.y);
        Y[1] = __floats2half2_rn(v.z, v.w);
        return;
    }
    const float* x = (z == 0) ? x0 : (z == 1) ? x1 : x2;
    __half* y = g_Act + (size_t)z * NELEM;
    int i = (blockIdx.x * blockDim.x + threadIdx.x) * 4;
    float4 v = *(const float4*)(x + i);
    __half2* Y = (__half2*)(y + i);
    Y[0] = __floats2half2_rn(v.x, v.y);
    Y[1] = __floats2half2_rn(v.z, v.w);
}

// ---------------- batched W (KxN) -> W^T (NxK) fp16 hi/lo (4 weights) ----
__global__ void transpose_split4(const float* __restrict__ w0, const float* __restrict__ w1,
                                 const float* __restrict__ w2, const float* __restrict__ w3)
{
    __shared__ float t[32][33];
    const int z = blockIdx.z;
    const float* W = (z == 0) ? w0 : (z == 1) ? w1 : (z == 2) ? w2 : w3;
    __half* Th = g_Wh + (size_t)z * DM * DM;
    __half* Tl = g_Wl + (size_t)z * DM * DM;
    const int tx = threadIdx.x, ty = threadIdx.y;
    t[ty][tx] = W[(blockIdx.y * 32 + ty) * DM + blockIdx.x * 32 + tx];
    __syncthreads();
    const int on = blockIdx.x * 32 + ty;
    const int ok = blockIdx.y * 32 + tx;
    const float v = t[tx][ty];
    __half h = __float2half_rn(v);
    Th[on * DM + ok] = h;
    Tl[on * DM + ok] = __float2half_rn(v - __half2float(h));
}

// =====================================================================
// fp16 HMMA GEMM: C = A @ (Bh [+ Bl])^T + bias. twopass selects split-B.
// 128x128 CTA tile, BK=64, 256 threads, double-buffered cp.async.
// =====================================================================
__global__ void __launch_bounds__(256) hmma_gemm2(
    GemmBatch gb,
    const __half* __restrict__ BhBase, const __half* __restrict__ BlBase,
    float* __restrict__ C,
    int M, int N, int K, int mode, int twopass)
{
    extern __shared__ char smc[];
    const uint32_t sb0 = smem_u32(smc);
    const uint32_t sbuf = (sb0 + 1023u) & ~1023u;

    const int z = blockIdx.z;
    const __half* A = gb.A[z];
    const float* bias = gb.bias[z];
    __half* Cf = gb.Cf[z];
    const __half* Bh = BhBase + (mode == MODE_HSPLIT ? (size_t)z * DM * DM : 0);
    const __half* Bl = BlBase ? BlBase + (mode == MODE_HSPLIT ? (size_t)z * DM * DM : 0) : nullptr;

    const int tid = threadIdx.x;
    const int wid = tid >> 5, lane = tid & 31;
    const int wm = wid & 3, wn = wid >> 2;
    const int bm = blockIdx.y << 7, bn = blockIdx.x << 7;

    float acc[2][8][4];
#pragma unroll
    for (int i = 0; i < 2; i++)
#pragma unroll
        for (int j = 0; j < 8; j++)
#pragma unroll
            for (int k = 0; k < 4; k++) acc[i][j][k] = 0.f;

    const int nc = K >> 6;

    auto issue_chunk = [&](int c) {
        const int k0 = c << 6;
        const uint32_t bufb = sbuf + (uint32_t)(c & 1) * 49152u;
#pragma unroll
        for (int t = 0; t < 4; t++) {
            const int u = tid + (t << 8);
            const int row = u >> 3, i = u & 7;
            const uint32_t so = swz((uint32_t)(row * 128 + i * 16));
            const size_t aoff = (((size_t)(bm + row) * K + k0) >> 3) + i;
            cpasync16(bufb + so, (const uint4*)A + aoff, 16u);
            const int nr = bn + row;
            const size_t boff = (((size_t)nr * K + k0) >> 3) + i;
            const uint32_t bsz = (nr < N) ? 16u : 0u;
            cpasync16(bufb + 16384u + so, (const uint4*)Bh + boff, bsz);
            if (twopass)
                cpasync16(bufb + 32768u + so, (const uint4*)Bl + boff, bsz);
        }
        cp_commit();
    };

    issue_chunk(0);
    if (nc > 1) issue_chunk(1);

    for (int c = 0; c < nc; c++) {
        if (c + 1 < nc) {
            asm volatile("cp.async.wait_group 1;" ::: "memory");
        } else {
            asm volatile("cp.async.wait_group 0;" ::: "memory");
        }
        __syncthreads();

        const uint32_t bufb = sbuf + (uint32_t)(c & 1) * 49152u;
#pragma unroll
        for (int kk = 0; kk < 4; kk++) {
            const uint32_t kb = (uint32_t)(kk << 5);
            uint32_t a4[8];
#pragma unroll
            for (int mf = 0; mf < 2; mf++) {
                const uint32_t r = (uint32_t)(wm * 32 + mf * 16 + (lane & 15));
                ldmx4(a4 + mf * 4, bufb + swz(r * 128 + kb + (uint32_t)((lane >> 4) << 4)));
            }
            uint32_t bh[16], bl[16];
#pragma unroll
            for (int nf2 = 0; nf2 < 4; nf2++) {
                const uint32_t r = (uint32_t)(wn * 64 + nf2 * 16 + (lane & 7) + ((lane >> 4) << 3));
                const uint32_t adr = swz(r * 128 + kb + (uint32_t)(((lane >> 3) & 1) << 4));
                ldmx4(bh + nf2 * 4, bufb + 16384u + adr);
                if (twopass) ldmx4(bl + nf2 * 4, bufb + 32768u + adr);
            }
#pragma unroll
            for (int mf = 0; mf < 2; mf++)
#pragma unroll
                for (int nf = 0; nf < 8; nf++) {
                    const int bi = (nf >> 1) * 4 + (nf & 1) * 2;
                    mma_f16(acc[mf][nf], a4 + mf * 4, bh + bi);
                    if (twopass) mma_f16(acc[mf][nf], a4 + mf * 4, bl + bi);
                }
        }
        __syncthreads();
        if (c + 2 < nc) issue_chunk(c + 2);
    }

    // ---------------- epilogue ----------------
    const int gid = lane >> 2, tig = lane & 3;
#pragma unroll
    for (int mf = 0; mf < 2; mf++) {
        const int m0 = bm + wm * 32 + mf * 16 + gid;
#pragma unroll
        for (int nf = 0; nf < 8; nf++) {
            const int col = bn + wn * 64 + nf * 8 + tig * 2;
            float b0 = 0.f, b1 = 0.f;
            if (bias) { b0 = __ldg(bias + col); b1 = __ldg(bias + col + 1); }
            const float v00 = acc[mf][nf][0] + b0, v01 = acc[mf][nf][1] + b1;
            const float v10 = acc[mf][nf][2] + b0, v11 = acc[mf][nf][3] + b1;
            if (mode == MODE_HSPLIT) {
                const int h = col >> 6, d = col & 63;
                const int b_ = m0 >> 11, l0 = m0 & 2047;
                const size_t o0 = (((size_t)b_ * NH + h) * L_SEQ + l0) * HD + d;
                const size_t o1 = o0 + (size_t)8 * HD;
                *(__half2*)(Cf + o0) = __floats2half2_rn(v00, v01);
                *(__half2*)(Cf + o1) = __floats2half2_rn(v10, v11);
            } else if (mode == MODE_PLAIN) {
                *(float2*)(C + (size_t)m0 * N + col) = make_float2(v00, v01);
                *(float2*)(C + (size_t)(m0 + 8) * N + col) = make_float2(v10, v11);
            } else { // MODE_QREL
                if (col + 1 < N) {
                    *(__half2*)(Cf + (size_t)m0 * QRP + col) = __floats2half2_rn(v00, v01);
                    *(__half2*)(Cf + (size_t)(m0 + 8) * QRP + col) = __floats2half2_rn(v10, v11);
                } else if (col < N) {
                    Cf[(size_t)m0 * QRP + col] = __float2half_rn(v00);
                    Cf[(size_t)(m0 + 8) * QRP + col] = __float2half_rn(v10);
                }
            }
        }
    }
}

// =====================================================================
// Flash attention, fp16 HMMA, register P fragments, cp.async-pipelined K/V.
// Grid (L/128, BH), 256 threads. smem: Q 16K | 2 x (K 16K + V 16K) = 80K.
// =====================================================================
#define FLASH_SMEM_BYTES 81920
#define NTILES (L_SEQ / 128)
__global__ void __launch_bounds__(256) flash_f16()
{
    extern __shared__ char smc[];
    const uint32_t sb = smem_u32(smc);
    const uint32_t uQ = sb;

    const int tid = threadIdx.x, w = tid >> 5, lane = tid & 31;
    const int tig = lane & 3, grp = lane >> 2;
    const int bh = blockIdx.y, i0 = blockIdx.x << 7;

    const uint4* gQ = (const uint4*)(g_Qf + (size_t)(bh * L_SEQ + i0) * HD);
    const uint4* gK = (const uint4*)(g_Kf + (size_t)bh * L_SEQ * HD);
    const uint4* gV = (const uint4*)(g_Vf + (size_t)bh * L_SEQ * HD);

    auto issue_kv = [&](int c) {
        const uint32_t uB = sb + 16384u + (uint32_t)(c & 1) * 32768u;
#pragma unroll
        for (int t = 0; t < 4; t++) {
            const int u = tid + (t << 8);
            const int r = u >> 3, i = u & 7;
            const uint32_t so = swz((uint32_t)(r * 128 + i * 16));
            const size_t gi = (size_t)(c * 128 + r) * 8 + i;
            cpasync16(uB + so, gK + gi, 16u);
            cpasync16(uB + 16384u + so, gV + gi, 16u);
        }
        cp_commit();
    };

    // prologue: Q + KV0 as group 0, KV1 as group 1
#pragma unroll
    for (int t = 0; t < 4; t++) {
        const int u = tid + (t << 8);
        const int r = u >> 3, i = u & 7;
        cpasync16(uQ + swz((uint32_t)(r * 128 + i * 16)), gQ + r * 8 + i, 16u);
    }
    issue_kv(0);   // commits Q+KV0 together
    issue_kv(1);

    float O[8][4];
#pragma unroll
    for (int i = 0; i < 8; i++)
#pragma unroll
        for (int j = 0; j < 4; j++) O[i][j] = 0.f;
    float m_a = -1e30f, m_b = -1e30f, l_a = 0.f, l_b = 0.f;

    const int ia = i0 + w * 16 + grp, ib = ia + 8;
    const __half* qra = g_qrel + (size_t)(bh * L_SEQ + ia) * QRP + 512;
    const __half* qrb = g_qrel + (size_t)(bh * L_SEQ + ib) * QRP + 512;

    const float SCL = 0.125f * 1.4426950408889634f;

    for (int c = 0; c < NTILES; c++) {
        const int j0 = c << 7;
        if (c + 1 < NTILES) {
            asm volatile("cp.async.wait_group 1;" ::: "memory");
        } else {
            asm volatile("cp.async.wait_group 0;" ::: "memory");
        }
        __syncthreads();
        const uint32_t uK = sb + 16384u + (uint32_t)(c & 1) * 32768u;
        const uint32_t uV = uK + 16384u;

        // ---- S = QK^T ----
        float s[16][4];
#pragma unroll
        for (int i = 0; i < 16; i++)
#pragma unroll
            for (int j = 0; j < 4; j++) s[i][j] = 0.f;

        const uint32_t ra = (uint32_t)(w * 16 + (lane & 15));
#pragma unroll
        for (int kk = 0; kk < 4; kk++) {
            const uint32_t kb = (uint32_t)(kk << 5);
            uint32_t q4[4];
            ldmx4(q4, uQ + swz(ra * 128 + kb + (uint32_t)((lane >> 4) << 4)));
#pragma unroll
            for (int g = 0; g < 8; g++) {
                const uint32_t rb = (uint32_t)(g * 16 + (lane & 7) + ((lane >> 4) << 3));
                uint32_t k4[4];
                ldmx4(k4, uK + swz(rb * 128 + kb + (uint32_t)(((lane >> 3) & 1) << 4)));
                mma_f16(s[2 * g],     q4, k4);
                mma_f16(s[2 * g + 1], q4, k4 + 2);
            }
        }

        // ---- + positional term (fp16 gather), scale into exp2 domain ----
#pragma unroll
        for (int nf = 0; nf < 16; nf++) {
            const int j = j0 + nf * 8 + tig * 2;
            const int e0a = min(max(j - ia, -512), 512);
            const int e1a = min(max(j + 1 - ia, -512), 512);
            const int e0b = min(max(j - ib, -512), 512);
            const int e1b = min(max(j + 1 - ib, -512), 512);
            s[nf][0] = (s[nf][0] + __half2float(__ldg(qra + e0a))) * SCL;
            s[nf][1] = (s[nf][1] + __half2float(__ldg(qra + e1a))) * SCL;
            s[nf][2] = (s[nf][2] + __half2float(__ldg(qrb + e0b))) * SCL;
            s[nf][3] = (s[nf][3] + __half2float(__ldg(qrb + e1b))) * SCL;
        }

        // ---- online softmax ----
        float ma = -1e30f, mb = -1e30f;
#pragma unroll
        for (int nf = 0; nf < 16; nf++) {
            ma = fmaxf(ma, fmaxf(s[nf][0], s[nf][1]));
            mb = fmaxf(mb, fmaxf(s[nf][2], s[nf][3]));
        }
        ma = fmaxf(ma, __shfl_xor_sync(0xffffffffu, ma, 1));
        ma = fmaxf(ma, __shfl_xor_sync(0xffffffffu, ma, 2));
        mb = fmaxf(mb, __shfl_xor_sync(0xffffffffu, mb, 1));
        mb = fmaxf(mb, __shfl_xor_sync(0xffffffffu, mb, 2));
        const float mna = fmaxf(m_a, ma), mnb = fmaxf(m_b, mb);
        const float ca = exp2f(m_a - mna), cb = exp2f(m_b - mnb);
        m_a = mna; m_b = mnb;

        // ---- exp2 + pack P directly into MMA A-fragments ----
        uint32_t pA[16], pB[16];
        float sa = 0.f, sb2 = 0.f;
#pragma unroll
        for (int nf = 0; nf < 16; nf++) {
            const float p0 = exp2f(s[nf][0] - m_a);
            const float p1 = exp2f(s[nf][1] - m_a);
            const float p2 = exp2f(s[nf][2] - m_b);
            const float p3 = exp2f(s[nf][3] - m_b);
            sa += p0 + p1;
            sb2 += p2 + p3;
            pA[nf] = packh2(p0, p1);
            pB[nf] = packh2(p2, p3);
        }
        sa += __shfl_xor_sync(0xffffffffu, sa, 1);
        sa += __shfl_xor_sync(0xffffffffu, sa, 2);
        sb2 += __shfl_xor_sync(0xffffffffu, sb2, 1);
        sb2 += __shfl_xor_sync(0xffffffffu, sb2, 2);
        l_a = l_a * ca + sa;
        l_b = l_b * cb + sb2;
#pragma unroll
        for (int nf2 = 0; nf2 < 8; nf2++) {
            O[nf2][0] *= ca; O[nf2][1] *= ca;
            O[nf2][2] *= cb; O[nf2][3] *= cb;
        }

        // ---- O += P V (P from registers) ----
#pragma unroll
        for (int k = 0; k < 8; k++) {
            uint32_t a4[4] = { pA[2 * k], pB[2 * k], pA[2 * k + 1], pB[2 * k + 1] };
#pragma unroll
            for (int g = 0; g < 4; g++) {
                const uint32_t rv = (uint32_t)(k * 16 + (lane & 7) + (((lane >> 3) & 1) << 3));
                uint32_t v4[4];
                ldmx4t(v4, uV + swz(rv * 128 + (uint32_t)(g * 32) + (uint32_t)((lane >> 4) << 4)));
                mma_f16(O[2 * g],     a4, v4);
                mma_f16(O[2 * g + 1], a4, v4 + 2);
            }
        }
        __syncthreads();
        if (c + 2 < NTILES) issue_kv(c + 2);
    }

    // ---- epilogue: normalize, write fp16 merged-head into g_Act slot 0 ----
    const float inva = 1.f / l_a, invb = 1.f / l_b;
    const int b_ = bh >> 4, h = bh & 15;
    const size_t rowa = (size_t)b_ * L_SEQ + (i0 + w * 16 + grp);
    const size_t rowb = rowa + 8;
#pragma unroll
    for (int nf2 = 0; nf2 < 8; nf2++) {
        const int col = h * 64 + nf2 * 8 + tig * 2;
        *(__half2*)(g_Act + rowa * DM + col) = __floats2half2_rn(O[nf2][0] * inva, O[nf2][1] * inva);
        *(__half2*)(g_Act + rowb * DM + col) = __floats2half2_rn(O[nf2][2] * invb, O[nf2][3] * invb);
    }
}

// =====================================================================
extern "C" void kernel_launch(void* const* d_in, const int* in_sizes, int n_in,
                              void* d_out, int out_size)
{
    const float* query = (const float*)d_in[0];
    const float* key   = (const float*)d_in[1];
    const float* value = (const float*)d_in[2];
    const float* wq    = (const float*)d_in[3];
    const float* bq    = (const float*)d_in[4];
    const float* wk    = (const float*)d_in[5];
    const float* bk    = (const float*)d_in[6];
    const float* wv    = (const float*)d_in[7];
    const float* bv    = (const float*)d_in[8];
    const float* wo    = (const float*)d_in[9];
    const float* bo    = (const float*)d_in[10];
    const float* rel   = (const float*)d_in[11];

    __half *pQrel, *pQf, *pKf, *pVf, *pAct, *pWh, *pWl, *pEf;
    cudaGetSymbolAddress((void**)&pQrel, g_qrel);
    cudaGetSymbolAddress((void**)&pQf, g_Qf);
    cudaGetSymbolAddress((void**)&pKf, g_Kf);
    cudaGetSymbolAddress((void**)&pVf, g_Vf);
    cudaGetSymbolAddress((void**)&pAct, g_Act);
    cudaGetSymbolAddress((void**)&pWh, g_Wh);
    cudaGetSymbolAddress((void**)&pWl, g_Wl);
    cudaGetSymbolAddress((void**)&pEf, g_Ef);

    const int GEMM_SMEM = 2 * 49152 + 1024;
    cudaFuncSetAttribute(hmma_gemm2, cudaFuncAttributeMaxDynamicSharedMemorySize, GEMM_SMEM);
    cudaFuncSetAttribute(flash_f16, cudaFuncAttributeMaxDynamicSharedMemorySize, FLASH_SMEM_BYTES);

    // ---- batched weight transposes + input/rel converts ----
    transpose_split4<<<dim3(32, 32, 4), dim3(32, 32)>>>(wq, wk, wv, wo);
    convert4_f16<<<dim3(4096, 4), 256>>>(query, key, value, rel);

    // ---- batched QKV projections (2-pass split weights) ----
    GemmBatch qkv;
    qkv.A[0] = pAct;  qkv.A[1] = pAct + NELEM;  qkv.A[2] = pAct + 2 * NELEM;
    qkv.bias[0] = bq; qkv.bias[1] = bk;         qkv.bias[2] = bv;
    qkv.Cf[0] = pQf;  qkv.Cf[1] = pKf;          qkv.Cf[2] = pVf;
    hmma_gemm2<<<dim3(8, 32, 3), 256, GEMM_SMEM>>>(qkv, pWh, pWl, nullptr,
                                                   MROWS, DM, DM, MODE_HSPLIT, 1);

    // ---- q_rel = Qf @ rel^T (1-pass fp16) ----
    GemmBatch qr;
    qr.A[0] = pQf;  qr.A[1] = pQf;  qr.A[2] = pQf;
    qr.bias[0] = nullptr; qr.bias[1] = nullptr; qr.bias[2] = nullptr;
    qr.Cf[0] = pQrel; qr.Cf[1] = pQrel; qr.Cf[2] = pQrel;
    hmma_gemm2<<<dim3(9, 512, 1), 256, GEMM_SMEM>>>(qr, pEf, nullptr, nullptr,
                                                    BH * L_SEQ, NEMB, HD, MODE_QREL, 0);

    // ---- attention -> g_Act slot 0 ----
    flash_f16<<<dim3(16, 32), 256, FLASH_SMEM_BYTES>>>();

    // ---- output projection (1-pass fp16, wo = slot 3) ----
    GemmBatch op;
    op.A[0] = pAct; op.A[1] = pAct; op.A[2] = pAct;
    op.bias[0] = bo; op.bias[1] = bo; op.bias[2] = bo;
    op.Cf[0] = nullptr; op.Cf[1] = nullptr; op.Cf[2] = nullptr;
    hmma_gemm2<<<dim3(8, 32, 1), 256, GEMM_SMEM>>>(op, pWh + (size_t)3 * DM * DM, nullptr,
                                                   (float*)d_out, MROWS, DM, DM, MODE_PLAIN, 0);
}

// round 11
// speedup vs baseline: 1.2242x; 1.2242x over previous
#include <cuda_runtime.h>
#include <cuda_fp16.h>
#include <stdint.h>
#include <math.h>

// Problem constants
#define L_SEQ 2048
#define DM    1024
#define NH    16
#define HD    64
#define BH    32
#define NEMB  1025
#define QRP   1056
#define MROWS 4096
#define NELEM (MROWS * DM)

#define MODE_PLAIN  0
#define MODE_HSPLIT 1

// ---------------- device scratch ----------------
__device__ __align__(16) __half g_qrel[BH * L_SEQ * QRP];
__device__ __align__(16) __half g_Qf[BH * L_SEQ * HD];
__device__ __align__(16) __half g_Kf[BH * L_SEQ * HD];
__device__ __align__(16) __half g_Vf[BH * L_SEQ * HD];
__device__ __align__(16) __half g_Act[3 * NELEM];      // q,k,v activations; slot 0 reused for attn out
__device__ __align__(16) __half g_Wh[4 * DM * DM];     // wq,wk,wv,wo transposed fp16
__device__ __align__(16) __half g_Ef[NEMB * HD];

struct GemmBatch {
    const __half* A[3];
    const float*  bias[3];
    __half*       Cf[3];
};

// ---------------- helpers ----------------
static __device__ __forceinline__ uint32_t smem_u32(const void* p) {
    uint32_t a;
    asm("{ .reg .u64 t; cvta.to.shared.u64 t, %1; cvt.u32.u64 %0, t; }" : "=r"(a) : "l"(p));
    return a;
}
static __device__ __forceinline__ uint32_t swz(uint32_t b) { return b ^ ((b >> 3) & 0x70); }

static __device__ __forceinline__ void ldmx4(uint32_t* r, uint32_t addr) {
    asm volatile("ldmatrix.sync.aligned.m8n8.x4.shared.b16 {%0,%1,%2,%3}, [%4];"
                 : "=r"(r[0]), "=r"(r[1]), "=r"(r[2]), "=r"(r[3]) : "r"(addr));
}
static __device__ __forceinline__ void ldmx4t(uint32_t* r, uint32_t addr) {
    asm volatile("ldmatrix.sync.aligned.m8n8.x4.trans.shared.b16 {%0,%1,%2,%3}, [%4];"
                 : "=r"(r[0]), "=r"(r[1]), "=r"(r[2]), "=r"(r[3]) : "r"(addr));
}
static __device__ __forceinline__ void mma_f16(float* c, const uint32_t* a, const uint32_t* b) {
    asm volatile("mma.sync.aligned.m16n8k16.row.col.f32.f16.f16.f32 "
                 "{%0,%1,%2,%3}, {%4,%5,%6,%7}, {%8,%9}, {%0,%1,%2,%3};"
                 : "+f"(c[0]), "+f"(c[1]), "+f"(c[2]), "+f"(c[3])
                 : "r"(a[0]), "r"(a[1]), "r"(a[2]), "r"(a[3]), "r"(b[0]), "r"(b[1]));
}
static __device__ __forceinline__ void cpasync16(uint32_t dst, const void* src, uint32_t ssz) {
    asm volatile("cp.async.cg.shared.global [%0], [%1], 16, %2;"
                 :: "r"(dst), "l"(src), "r"(ssz) : "memory");
}
static __device__ __forceinline__ void cp_commit() {
    asm volatile("cp.async.commit_group;" ::: "memory");
}
static __device__ __forceinline__ uint32_t packh2(float a, float b) {
    __half2 h = __floats2half2_rn(a, b);
    return *(uint32_t*)&h;
}

// ---------------- batched fp32 -> fp16 (q,k,v inputs + rel_emb) ----------------
__global__ void convert4_f16(const float* __restrict__ x0, const float* __restrict__ x1,
                             const float* __restrict__ x2, const float* __restrict__ x3)
{
    const int z = blockIdx.y;
    if (z == 3) {
        const int n = NEMB * HD;
        int i = (blockIdx.x * blockDim.x + threadIdx.x) * 4;
        if (i >= n) return;
        float4 v = *(const float4*)(x3 + i);
        __half2* Y = (__half2*)(g_Ef + i);
        Y[0] = __floats2half2_rn(v.x, v.y);
        Y[1] = __floats2half2_rn(v.z, v.w);
        return;
    }
    const float* x = (z == 0) ? x0 : (z == 1) ? x1 : x2;
    __half* y = g_Act + (size_t)z * NELEM;
    int i = (blockIdx.x * blockDim.x + threadIdx.x) * 4;
    float4 v = *(const float4*)(x + i);
    __half2* Y = (__half2*)(y + i);
    Y[0] = __floats2half2_rn(v.x, v.y);
    Y[1] = __floats2half2_rn(v.z, v.w);
}

// ---------------- batched W (KxN) -> W^T (NxK) fp16 (4 weights) ----------------
__global__ void transpose4(const float* __restrict__ w0, const float* __restrict__ w1,
                           const float* __restrict__ w2, const float* __restrict__ w3)
{
    __shared__ float t[32][33];
    const int z = blockIdx.z;
    const float* W = (z == 0) ? w0 : (z == 1) ? w1 : (z == 2) ? w2 : w3;
    __half* Th = g_Wh + (size_t)z * DM * DM;
    const int tx = threadIdx.x, ty = threadIdx.y;
    t[ty][tx] = W[(blockIdx.y * 32 + ty) * DM + blockIdx.x * 32 + tx];
    __syncthreads();
    const int on = blockIdx.x * 32 + ty;
    const int ok = blockIdx.y * 32 + tx;
    Th[on * DM + ok] = __float2half_rn(t[tx][ty]);
}

// =====================================================================
// 1-pass fp16 HMMA GEMM: C = A @ B^T + bias. Batched over grid.z.
// 128x128 CTA tile, BK=64, 256 threads, double-buffered cp.async.
// smem/chunk: A 16K | B 16K (stride 32768, x2 buffers)
// =====================================================================
__global__ void __launch_bounds__(256) hmma_gemm2(
    GemmBatch gb, const __half* __restrict__ BhBase,
    float* __restrict__ C,
    int M, int N, int K, int mode)
{
    extern __shared__ char smc[];
    const uint32_t sb0 = smem_u32(smc);
    const uint32_t sbuf = (sb0 + 1023u) & ~1023u;

    const int z = blockIdx.z;
    const __half* A = gb.A[z];
    const float* bias = gb.bias[z];
    __half* Cf = gb.Cf[z];
    const __half* Bh = BhBase + (mode == MODE_HSPLIT ? (size_t)z * DM * DM : 0);

    const int tid = threadIdx.x;
    const int wid = tid >> 5, lane = tid & 31;
    const int wm = wid & 3, wn = wid >> 2;
    const int bm = blockIdx.y << 7, bn = blockIdx.x << 7;

    float acc[2][8][4];
#pragma unroll
    for (int i = 0; i < 2; i++)
#pragma unroll
        for (int j = 0; j < 8; j++)
#pragma unroll
            for (int k = 0; k < 4; k++) acc[i][j][k] = 0.f;

    const int nc = K >> 6;

    auto issue_chunk = [&](int c) {
        const int k0 = c << 6;
        const uint32_t bufb = sbuf + (uint32_t)(c & 1) * 32768u;
#pragma unroll
        for (int t = 0; t < 4; t++) {
            const int u = tid + (t << 8);
            const int row = u >> 3, i = u & 7;
            const uint32_t so = swz((uint32_t)(row * 128 + i * 16));
            const size_t aoff = (((size_t)(bm + row) * K + k0) >> 3) + i;
            cpasync16(bufb + so, (const uint4*)A + aoff, 16u);
            const int nr = bn + row;
            const size_t boff = (((size_t)nr * K + k0) >> 3) + i;
            cpasync16(bufb + 16384u + so, (const uint4*)Bh + boff, (nr < N) ? 16u : 0u);
        }
        cp_commit();
    };

    issue_chunk(0);
    if (nc > 1) issue_chunk(1);

    for (int c = 0; c < nc; c++) {
        if (c + 1 < nc) {
            asm volatile("cp.async.wait_group 1;" ::: "memory");
        } else {
            asm volatile("cp.async.wait_group 0;" ::: "memory");
        }
        __syncthreads();

        const uint32_t bufb = sbuf + (uint32_t)(c & 1) * 32768u;
#pragma unroll
        for (int kk = 0; kk < 4; kk++) {
            const uint32_t kb = (uint32_t)(kk << 5);
            uint32_t a4[8];
#pragma unroll
            for (int mf = 0; mf < 2; mf++) {
                const uint32_t r = (uint32_t)(wm * 32 + mf * 16 + (lane & 15));
                ldmx4(a4 + mf * 4, bufb + swz(r * 128 + kb + (uint32_t)((lane >> 4) << 4)));
            }
            uint32_t bh[16];
#pragma unroll
            for (int nf2 = 0; nf2 < 4; nf2++) {
                const uint32_t r = (uint32_t)(wn * 64 + nf2 * 16 + (lane & 7) + ((lane >> 4) << 3));
                ldmx4(bh + nf2 * 4, bufb + 16384u + swz(r * 128 + kb + (uint32_t)(((lane >> 3) & 1) << 4)));
            }
#pragma unroll
            for (int mf = 0; mf < 2; mf++)
#pragma unroll
                for (int nf = 0; nf < 8; nf++)
                    mma_f16(acc[mf][nf], a4 + mf * 4, bh + (nf >> 1) * 4 + (nf & 1) * 2);
        }
        __syncthreads();
        if (c + 2 < nc) issue_chunk(c + 2);
    }

    // ---------------- epilogue ----------------
    const int gid = lane >> 2, tig = lane & 3;
#pragma unroll
    for (int mf = 0; mf < 2; mf++) {
        const int m0 = bm + wm * 32 + mf * 16 + gid;
#pragma unroll
        for (int nf = 0; nf < 8; nf++) {
            const int col = bn + wn * 64 + nf * 8 + tig * 2;
            const float b0 = __ldg(bias + col), b1 = __ldg(bias + col + 1);
            const float v00 = acc[mf][nf][0] + b0, v01 = acc[mf][nf][1] + b1;
            const float v10 = acc[mf][nf][2] + b0, v11 = acc[mf][nf][3] + b1;
            if (mode == MODE_HSPLIT) {
                const int h = col >> 6, d = col & 63;
                const int b_ = m0 >> 11, l0 = m0 & 2047;
                const size_t o0 = (((size_t)b_ * NH + h) * L_SEQ + l0) * HD + d;
                const size_t o1 = o0 + (size_t)8 * HD;
                *(__half2*)(Cf + o0) = __floats2half2_rn(v00, v01);
                *(__half2*)(Cf + o1) = __floats2half2_rn(v10, v11);
            } else {
                *(float2*)(C + (size_t)m0 * N + col) = make_float2(v00, v01);
                *(float2*)(C + (size_t)(m0 + 8) * N + col) = make_float2(v10, v11);
            }
        }
    }
}

// =====================================================================
// Dedicated qrel GEMM: qrel[bm..bm+128, 0..1025] = Q(128x64) @ E(1025x64)^T.
// One CTA per 128-row block; A smem-resident + reg fragments; 9 B column
// tiles double-buffered via cp.async; epilogue overlaps next B load.
// smem: A 16K | 2 x B 16K = 48K (+align)
// =====================================================================
#define QR_NT 9
#define QR_SMEM (49152 + 1024)
__global__ void __launch_bounds__(256) qrel_gemm()
{
    extern __shared__ char smc[];
    const uint32_t sb0 = smem_u32(smc);
    const uint32_t sbuf = (sb0 + 1023u) & ~1023u;
    const uint32_t uA = sbuf, uB = sbuf + 16384u;

    const int tid = threadIdx.x;
    const int wid = tid >> 5, lane = tid & 31;
    const int wm = wid & 3, wn = wid >> 2;
    const int bm = blockIdx.x << 7;
    const int gid = lane >> 2, tig = lane & 3;

    auto issue_b = [&](int t) {
        const uint32_t dst = uB + (uint32_t)(t & 1) * 16384u;
#pragma unroll
        for (int q = 0; q < 4; q++) {
            const int u = tid + (q << 8);
            const int r = u >> 3, i = u & 7;
            const int nr = t * 128 + r;
            cpasync16(dst + swz((uint32_t)(r * 128 + i * 16)),
                      (const uint4*)g_Ef + (size_t)nr * 8 + i, (nr < NEMB) ? 16u : 0u);
        }
        cp_commit();
    };

    // prologue: A + B0 as one group, B1 as second
#pragma unroll
    for (int q = 0; q < 4; q++) {
        const int u = tid + (q << 8);
        const int r = u >> 3, i = u & 7;
        cpasync16(uA + swz((uint32_t)(r * 128 + i * 16)),
                  (const uint4*)g_Qf + (size_t)(bm + r) * 8 + i, 16u);
    }
    issue_b(0);     // commits A+B0
    issue_b(1);

    uint32_t a4[2][4][4];   // [mf][kk][frag]

    for (int t = 0; t < QR_NT; t++) {
        if (t + 1 < QR_NT) {
            asm volatile("cp.async.wait_group 1;" ::: "memory");
        } else {
            asm volatile("cp.async.wait_group 0;" ::: "memory");
        }
        __syncthreads();

        if (t == 0) {
#pragma unroll
            for (int kk = 0; kk < 4; kk++) {
                const uint32_t kb = (uint32_t)(kk << 5);
#pragma unroll
                for (int mf = 0; mf < 2; mf++) {
                    const uint32_t r = (uint32_t)(wm * 32 + mf * 16 + (lane & 15));
                    ldmx4(a4[mf][kk], uA + swz(r * 128 + kb + (uint32_t)((lane >> 4) << 4)));
                }
            }
        }

        const uint32_t uBt = uB + (uint32_t)(t & 1) * 16384u;
        float acc[2][8][4];
#pragma unroll
        for (int i = 0; i < 2; i++)
#pragma unroll
            for (int j = 0; j < 8; j++)
#pragma unroll
                for (int k = 0; k < 4; k++) acc[i][j][k] = 0.f;

#pragma unroll
        for (int kk = 0; kk < 4; kk++) {
            const uint32_t kb = (uint32_t)(kk << 5);
            uint32_t bh[16];
#pragma unroll
            for (int nf2 = 0; nf2 < 4; nf2++) {
                const uint32_t r = (uint32_t)(wn * 64 + nf2 * 16 + (lane & 7) + ((lane >> 4) << 3));
                ldmx4(bh + nf2 * 4, uBt + swz(r * 128 + kb + (uint32_t)(((lane >> 3) & 1) << 4)));
            }
#pragma unroll
            for (int mf = 0; mf < 2; mf++)
#pragma unroll
                for (int nf = 0; nf < 8; nf++)
                    mma_f16(acc[mf][nf], a4[mf][kk], bh + (nf >> 1) * 4 + (nf & 1) * 2);
        }
        __syncthreads();
        if (t + 2 < QR_NT) issue_b(t + 2);

        // epilogue for this column tile (overlaps next B load)
#pragma unroll
        for (int mf = 0; mf < 2; mf++) {
            const int m0 = bm + wm * 32 + mf * 16 + gid;
#pragma unroll
            for (int nf = 0; nf < 8; nf++) {
                const int col = t * 128 + wn * 64 + nf * 8 + tig * 2;
                if (col + 1 < NEMB) {
                    *(__half2*)(g_qrel + (size_t)m0 * QRP + col) =
                        __floats2half2_rn(acc[mf][nf][0], acc[mf][nf][1]);
                    *(__half2*)(g_qrel + (size_t)(m0 + 8) * QRP + col) =
                        __floats2half2_rn(acc[mf][nf][2], acc[mf][nf][3]);
                } else if (col < NEMB) {
                    g_qrel[(size_t)m0 * QRP + col] = __float2half_rn(acc[mf][nf][0]);
                    g_qrel[(size_t)(m0 + 8) * QRP + col] = __float2half_rn(acc[mf][nf][2]);
                }
            }
        }
    }
}

// =====================================================================
// Flash attention, fp16 HMMA, register P fragments, cp.async-pipelined K/V.
// Grid (L/128, BH), 256 threads. smem: Q 16K | 2 x (K 16K + V 16K) = 80K.
// =====================================================================
#define FLASH_SMEM_BYTES 81920
#define NTILES (L_SEQ / 128)
__global__ void __launch_bounds__(256) flash_f16()
{
    extern __shared__ char smc[];
    const uint32_t sb = smem_u32(smc);
    const uint32_t uQ = sb;

    const int tid = threadIdx.x, w = tid >> 5, lane = tid & 31;
    const int tig = lane & 3, grp = lane >> 2;
    const int bh = blockIdx.y, i0 = blockIdx.x << 7;

    const uint4* gQ = (const uint4*)(g_Qf + (size_t)(bh * L_SEQ + i0) * HD);
    const uint4* gK = (const uint4*)(g_Kf + (size_t)bh * L_SEQ * HD);
    const uint4* gV = (const uint4*)(g_Vf + (size_t)bh * L_SEQ * HD);

    auto issue_kv = [&](int c) {
        const uint32_t uB = sb + 16384u + (uint32_t)(c & 1) * 32768u;
#pragma unroll
        for (int t = 0; t < 4; t++) {
            const int u = tid + (t << 8);
            const int r = u >> 3, i = u & 7;
            const uint32_t so = swz((uint32_t)(r * 128 + i * 16));
            const size_t gi = (size_t)(c * 128 + r) * 8 + i;
            cpasync16(uB + so, gK + gi, 16u);
            cpasync16(uB + 16384u + so, gV + gi, 16u);
        }
        cp_commit();
    };

#pragma unroll
    for (int t = 0; t < 4; t++) {
        const int u = tid + (t << 8);
        const int r = u >> 3, i = u & 7;
        cpasync16(uQ + swz((uint32_t)(r * 128 + i * 16)), gQ + r * 8 + i, 16u);
    }
    issue_kv(0);
    issue_kv(1);

    float O[8][4];
#pragma unroll
    for (int i = 0; i < 8; i++)
#pragma unroll
        for (int j = 0; j < 4; j++) O[i][j] = 0.f;
    float m_a = -1e30f, m_b = -1e30f, l_a = 0.f, l_b = 0.f;

    const int ia = i0 + w * 16 + grp, ib = ia + 8;
    const __half* qra = g_qrel + (size_t)(bh * L_SEQ + ia) * QRP + 512;
    const __half* qrb = g_qrel + (size_t)(bh * L_SEQ + ib) * QRP + 512;

    const float SCL = 0.125f * 1.4426950408889634f;

    for (int c = 0; c < NTILES; c++) {
        const int j0 = c << 7;
        if (c + 1 < NTILES) {
            asm volatile("cp.async.wait_group 1;" ::: "memory");
        } else {
            asm volatile("cp.async.wait_group 0;" ::: "memory");
        }
        __syncthreads();
        const uint32_t uK = sb + 16384u + (uint32_t)(c & 1) * 32768u;
        const uint32_t uV = uK + 16384u;

        float s[16][4];
#pragma unroll
        for (int i = 0; i < 16; i++)
#pragma unroll
            for (int j = 0; j < 4; j++) s[i][j] = 0.f;

        const uint32_t ra = (uint32_t)(w * 16 + (lane & 15));
#pragma unroll
        for (int kk = 0; kk < 4; kk++) {
            const uint32_t kb = (uint32_t)(kk << 5);
            uint32_t q4[4];
            ldmx4(q4, uQ + swz(ra * 128 + kb + (uint32_t)((lane >> 4) << 4)));
#pragma unroll
            for (int g = 0; g < 8; g++) {
                const uint32_t rb = (uint32_t)(g * 16 + (lane & 7) + ((lane >> 4) << 3));
                uint32_t k4[4];
                ldmx4(k4, uK + swz(rb * 128 + kb + (uint32_t)(((lane >> 3) & 1) << 4)));
                mma_f16(s[2 * g],     q4, k4);
                mma_f16(s[2 * g + 1], q4, k4 + 2);
            }
        }

#pragma unroll
        for (int nf = 0; nf < 16; nf++) {
            const int j = j0 + nf * 8 + tig * 2;
            const int e0a = min(max(j - ia, -512), 512);
            const int e1a = min(max(j + 1 - ia, -512), 512);
            const int e0b = min(max(j - ib, -512), 512);
            const int e1b = min(max(j + 1 - ib, -512), 512);
            s[nf][0] = (s[nf][0] + __half2float(__ldg(qra + e0a))) * SCL;
            s[nf][1] = (s[nf][1] + __half2float(__ldg(qra + e1a))) * SCL;
            s[nf][2] = (s[nf][2] + __half2float(__ldg(qrb + e0b))) * SCL;
            s[nf][3] = (s[nf][3] + __half2float(__ldg(qrb + e1b))) * SCL;
        }

        float ma = -1e30f, mb = -1e30f;
#pragma unroll
        for (int nf = 0; nf < 16; nf++) {
            ma = fmaxf(ma, fmaxf(s[nf][0], s[nf][1]));
            mb = fmaxf(mb, fmaxf(s[nf][2], s[nf][3]));
        }
        ma = fmaxf(ma, __shfl_xor_sync(0xffffffffu, ma, 1));
        ma = fmaxf(ma, __shfl_xor_sync(0xffffffffu, ma, 2));
        mb = fmaxf(mb, __shfl_xor_sync(0xffffffffu, mb, 1));
        mb = fmaxf(mb, __shfl_xor_sync(0xffffffffu, mb, 2));
        const float mna = fmaxf(m_a, ma), mnb = fmaxf(m_b, mb);
        const float ca = exp2f(m_a - mna), cb = exp2f(m_b - mnb);
        m_a = mna; m_b = mnb;

        uint32_t pA[16], pB[16];
        float sa = 0.f, sb2 = 0.f;
#pragma unroll
        for (int nf = 0; nf < 16; nf++) {
            const float p0 = exp2f(s[nf][0] - m_a);
            const float p1 = exp2f(s[nf][1] - m_a);
            const float p2 = exp2f(s[nf][2] - m_b);
            const float p3 = exp2f(s[nf][3] - m_b);
            sa += p0 + p1;
            sb2 += p2 + p3;
            pA[nf] = packh2(p0, p1);
            pB[nf] = packh2(p2, p3);
        }
        sa += __shfl_xor_sync(0xffffffffu, sa, 1);
        sa += __shfl_xor_sync(0xffffffffu, sa, 2);
        sb2 += __shfl_xor_sync(0xffffffffu, sb2, 1);
        sb2 += __shfl_xor_sync(0xffffffffu, sb2, 2);
        l_a = l_a * ca + sa;
        l_b = l_b * cb + sb2;
#pragma unroll
        for (int nf2 = 0; nf2 < 8; nf2++) {
            O[nf2][0] *= ca; O[nf2][1] *= ca;
            O[nf2][2] *= cb; O[nf2][3] *= cb;
        }

#pragma unroll
        for (int k = 0; k < 8; k++) {
            uint32_t a4[4] = { pA[2 * k], pB[2 * k], pA[2 * k + 1], pB[2 * k + 1] };
#pragma unroll
            for (int g = 0; g < 4; g++) {
                const uint32_t rv = (uint32_t)(k * 16 + (lane & 7) + (((lane >> 3) & 1) << 3));
                uint32_t v4[4];
                ldmx4t(v4, uV + swz(rv * 128 + (uint32_t)(g * 32) + (uint32_t)((lane >> 4) << 4)));
                mma_f16(O[2 * g],     a4, v4);
                mma_f16(O[2 * g + 1], a4, v4 + 2);
            }
        }
        __syncthreads();
        if (c + 2 < NTILES) issue_kv(c + 2);
    }

    const float inva = 1.f / l_a, invb = 1.f / l_b;
    const int b_ = bh >> 4, h = bh & 15;
    const size_t rowa = (size_t)b_ * L_SEQ + (i0 + w * 16 + grp);
    const size_t rowb = rowa + 8;
#pragma unroll
    for (int nf2 = 0; nf2 < 8; nf2++) {
        const int col = h * 64 + nf2 * 8 + tig * 2;
        *(__half2*)(g_Act + rowa * DM + col) = __floats2half2_rn(O[nf2][0] * inva, O[nf2][1] * inva);
        *(__half2*)(g_Act + rowb * DM + col) = __floats2half2_rn(O[nf2][2] * invb, O[nf2][3] * invb);
    }
}

// =====================================================================
extern "C" void kernel_launch(void* const* d_in, const int* in_sizes, int n_in,
                              void* d_out, int out_size)
{
    const float* query = (const float*)d_in[0];
    const float* key   = (const float*)d_in[1];
    const float* value = (const float*)d_in[2];
    const float* wq    = (const float*)d_in[3];
    const float* bq    = (const float*)d_in[4];
    const float* wk    = (const float*)d_in[5];
    const float* bk    = (const float*)d_in[6];
    const float* wv    = (const float*)d_in[7];
    const float* bv    = (const float*)d_in[8];
    const float* wo    = (const float*)d_in[9];
    const float* bo    = (const float*)d_in[10];
    const float* rel   = (const float*)d_in[11];

    __half *pQf, *pKf, *pVf, *pAct, *pWh;
    cudaGetSymbolAddress((void**)&pQf, g_Qf);
    cudaGetSymbolAddress((void**)&pKf, g_Kf);
    cudaGetSymbolAddress((void**)&pVf, g_Vf);
    cudaGetSymbolAddress((void**)&pAct, g_Act);
    cudaGetSymbolAddress((void**)&pWh, g_Wh);

    const int GEMM_SMEM = 2 * 32768 + 1024;   // 66560
    cudaFuncSetAttribute(hmma_gemm2, cudaFuncAttributeMaxDynamicSharedMemorySize, GEMM_SMEM);
    cudaFuncSetAttribute(qrel_gemm, cudaFuncAttributeMaxDynamicSharedMemorySize, QR_SMEM);
    cudaFuncSetAttribute(flash_f16, cudaFuncAttributeMaxDynamicSharedMemorySize, FLASH_SMEM_BYTES);

    // ---- batched weight transposes + input/rel converts ----
    transpose4<<<dim3(32, 32, 4), dim3(32, 32)>>>(wq, wk, wv, wo);
    convert4_f16<<<dim3(4096, 4), 256>>>(query, key, value, rel);

    // ---- batched QKV projections (1-pass fp16) ----
    GemmBatch qkv;
    qkv.A[0] = pAct;  qkv.A[1] = pAct + NELEM;  qkv.A[2] = pAct + 2 * NELEM;
    qkv.bias[0] = bq; qkv.bias[1] = bk;         qkv.bias[2] = bv;
    qkv.Cf[0] = pQf;  qkv.Cf[1] = pKf;          qkv.Cf[2] = pVf;
    hmma_gemm2<<<dim3(8, 32, 3), 256, GEMM_SMEM>>>(qkv, pWh, nullptr,
                                                   MROWS, DM, DM, MODE_HSPLIT);

    // ---- q_rel = Qf @ rel^T (dedicated, A-resident) ----
    qrel_gemm<<<512, 256, QR_SMEM>>>();

    // ---- attention -> g_Act slot 0 ----
    flash_f16<<<dim3(16, 32), 256, FLASH_SMEM_BYTES>>>();

    // ---- output projection (1-pass fp16, wo = slot 3) ----
    GemmBatch op;
    op.A[0] = pAct; op.A[1] = pAct; op.A[2] = pAct;
    op.bias[0] = bo; op.bias[1] = bo; op.bias[2] = bo;
    op.Cf[0] = nullptr; op.Cf[1] = nullptr; op.Cf[2] = nullptr;
    hmma_gemm2<<<dim3(8, 32, 1), 256, GEMM_SMEM>>>(op, pWh + (size_t)3 * DM * DM,
                                                   (float*)d_out, MROWS, DM, DM, MODE_PLAIN);
}

// round 13
// speedup vs baseline: 1.3431x; 1.0971x over previous
#include <cuda_runtime.h>
#include <cuda_fp16.h>
#include <stdint.h>
#include <math.h>

// Problem constants
#define L_SEQ 2048
#define DM    1024
#define NH    16
#define HD    64
#define BH    32
#define NEMB  1025
#define QRP   1056
#define MROWS 4096
#define NELEM (MROWS * DM)

#define MODE_PLAIN  0
#define MODE_HSPLIT 1

// ---------------- device scratch ----------------
__device__ __align__(16) __half g_qrel[BH * L_SEQ * QRP];
__device__ __align__(16) __half g_Qf[BH * L_SEQ * HD];
__device__ __align__(16) __half g_Kf[BH * L_SEQ * HD];
__device__ __align__(16) __half g_Vf[BH * L_SEQ * HD];
__device__ __align__(16) __half g_Act[3 * NELEM];
__device__ __align__(16) __half g_Wh[4 * DM * DM];
__device__ __align__(16) __half g_Ef[NEMB * HD];

struct GemmBatch {
    const __half* A[3];
    const float*  bias[3];
    __half*       Cf[3];
};

// ---------------- helpers ----------------
static __device__ __forceinline__ uint32_t smem_u32(const void* p) {
    uint32_t a;
    asm("{ .reg .u64 t; cvta.to.shared.u64 t, %1; cvt.u32.u64 %0, t; }" : "=r"(a) : "l"(p));
    return a;
}
static __device__ __forceinline__ uint32_t swz(uint32_t b) { return b ^ ((b >> 3) & 0x70); }

static __device__ __forceinline__ void ldmx4(uint32_t* r, uint32_t addr) {
    asm volatile("ldmatrix.sync.aligned.m8n8.x4.shared.b16 {%0,%1,%2,%3}, [%4];"
                 : "=r"(r[0]), "=r"(r[1]), "=r"(r[2]), "=r"(r[3]) : "r"(addr));
}
static __device__ __forceinline__ void ldmx4t(uint32_t* r, uint32_t addr) {
    asm volatile("ldmatrix.sync.aligned.m8n8.x4.trans.shared.b16 {%0,%1,%2,%3}, [%4];"
                 : "=r"(r[0]), "=r"(r[1]), "=r"(r[2]), "=r"(r[3]) : "r"(addr));
}
static __device__ __forceinline__ void mma_f16(float* c, const uint32_t* a, const uint32_t* b) {
    asm volatile("mma.sync.aligned.m16n8k16.row.col.f32.f16.f16.f32 "
                 "{%0,%1,%2,%3}, {%4,%5,%6,%7}, {%8,%9}, {%0,%1,%2,%3};"
                 : "+f"(c[0]), "+f"(c[1]), "+f"(c[2]), "+f"(c[3])
                 : "r"(a[0]), "r"(a[1]), "r"(a[2]), "r"(a[3]), "r"(b[0]), "r"(b[1]));
}
static __device__ __forceinline__ void cpasync16(uint32_t dst, const void* src, uint32_t ssz) {
    asm volatile("cp.async.cg.shared.global [%0], [%1], 16, %2;"
                 :: "r"(dst), "l"(src), "r"(ssz) : "memory");
}
static __device__ __forceinline__ void cp_commit() {
    asm volatile("cp.async.commit_group;" ::: "memory");
}
static __device__ __forceinline__ uint32_t packh2(float a, float b) {
    __half2 h = __floats2half2_rn(a, b);
    return *(uint32_t*)&h;
}

// ---------------- batched fp32 -> fp16 (q,k,v inputs + rel_emb) ----------------
__global__ void convert4_f16(const float* __restrict__ x0, const float* __restrict__ x1,
                             const float* __restrict__ x2, const float* __restrict__ x3)
{
    const int z = blockIdx.y;
    if (z == 3) {
        const int n = NEMB * HD;
        int i = (blockIdx.x * blockDim.x + threadIdx.x) * 4;
        if (i >= n) return;
        float4 v = *(const float4*)(x3 + i);
        __half2* Y = (__half2*)(g_Ef + i);
        Y[0] = __floats2half2_rn(v.x, v.y);
        Y[1] = __floats2half2_rn(v.z, v.w);
        return;
    }
    const float* x = (z == 0) ? x0 : (z == 1) ? x1 : x2;
    __half* y = g_Act + (size_t)z * NELEM;
    int i = (blockIdx.x * blockDim.x + threadIdx.x) * 4;
    float4 v = *(const float4*)(x + i);
    __half2* Y = (__half2*)(y + i);
    Y[0] = __floats2half2_rn(v.x, v.y);
    Y[1] = __floats2half2_rn(v.z, v.w);
}

// ---------------- batched W (KxN) -> W^T (NxK) fp16 (4 weights) ----------------
__global__ void transpose4(const float* __restrict__ w0, const float* __restrict__ w1,
                           const float* __restrict__ w2, const float* __restrict__ w3)
{
    __shared__ float t[32][33];
    const int z = blockIdx.z;
    const float* W = (z == 0) ? w0 : (z == 1) ? w1 : (z == 2) ? w2 : w3;
    __half* Th = g_Wh + (size_t)z * DM * DM;
    const int tx = threadIdx.x, ty = threadIdx.y;
    t[ty][tx] = W[(blockIdx.y * 32 + ty) * DM + blockIdx.x * 32 + tx];
    __syncthreads();
    const int on = blockIdx.x * 32 + ty;
    const int ok = blockIdx.y * 32 + tx;
    Th[on * DM + ok] = __float2half_rn(t[tx][ty]);
}

// =====================================================================
// 1-pass fp16 HMMA GEMM: C = A @ B^T + bias. Batched over grid.z.
// =====================================================================
__global__ void __launch_bounds__(256) hmma_gemm2(
    GemmBatch gb, const __half* __restrict__ BhBase,
    float* __restrict__ C,
    int M, int N, int K, int mode)
{
    extern __shared__ char smc[];
    const uint32_t sb0 = smem_u32(smc);
    const uint32_t sbuf = (sb0 + 1023u) & ~1023u;

    const int z = blockIdx.z;
    const __half* A = gb.A[z];
    const float* bias = gb.bias[z];
    __half* Cf = gb.Cf[z];
    const __half* Bh = BhBase + (mode == MODE_HSPLIT ? (size_t)z * DM * DM : 0);

    const int tid = threadIdx.x;
    const int wid = tid >> 5, lane = tid & 31;
    const int wm = wid & 3, wn = wid >> 2;
    const int bm = blockIdx.y << 7, bn = blockIdx.x << 7;

    float acc[2][8][4];
#pragma unroll
    for (int i = 0; i < 2; i++)
#pragma unroll
        for (int j = 0; j < 8; j++)
#pragma unroll
            for (int k = 0; k < 4; k++) acc[i][j][k] = 0.f;

    const int nc = K >> 6;

    auto issue_chunk = [&](int c) {
        const int k0 = c << 6;
        const uint32_t bufb = sbuf + (uint32_t)(c & 1) * 32768u;
#pragma unroll
        for (int t = 0; t < 4; t++) {
            const int u = tid + (t << 8);
            const int row = u >> 3, i = u & 7;
            const uint32_t so = swz((uint32_t)(row * 128 + i * 16));
            const size_t aoff = (((size_t)(bm + row) * K + k0) >> 3) + i;
            cpasync16(bufb + so, (const uint4*)A + aoff, 16u);
            const int nr = bn + row;
            const size_t boff = (((size_t)nr * K + k0) >> 3) + i;
            cpasync16(bufb + 16384u + so, (const uint4*)Bh + boff, (nr < N) ? 16u : 0u);
        }
        cp_commit();
    };

    issue_chunk(0);
    if (nc > 1) issue_chunk(1);

    for (int c = 0; c < nc; c++) {
        if (c + 1 < nc) {
            asm volatile("cp.async.wait_group 1;" ::: "memory");
        } else {
            asm volatile("cp.async.wait_group 0;" ::: "memory");
        }
        __syncthreads();

        const uint32_t bufb = sbuf + (uint32_t)(c & 1) * 32768u;
#pragma unroll
        for (int kk = 0; kk < 4; kk++) {
            const uint32_t kb = (uint32_t)(kk << 5);
            uint32_t a4[8];
#pragma unroll
            for (int mf = 0; mf < 2; mf++) {
                const uint32_t r = (uint32_t)(wm * 32 + mf * 16 + (lane & 15));
                ldmx4(a4 + mf * 4, bufb + swz(r * 128 + kb + (uint32_t)((lane >> 4) << 4)));
            }
            uint32_t bh[16];
#pragma unroll
            for (int nf2 = 0; nf2 < 4; nf2++) {
                const uint32_t r = (uint32_t)(wn * 64 + nf2 * 16 + (lane & 7) + ((lane >> 4) << 3));
                ldmx4(bh + nf2 * 4, bufb + 16384u + swz(r * 128 + kb + (uint32_t)(((lane >> 3) & 1) << 4)));
            }
#pragma unroll
            for (int mf = 0; mf < 2; mf++)
#pragma unroll
                for (int nf = 0; nf < 8; nf++)
                    mma_f16(acc[mf][nf], a4 + mf * 4, bh + (nf >> 1) * 4 + (nf & 1) * 2);
        }
        __syncthreads();
        if (c + 2 < nc) issue_chunk(c + 2);
    }

    const int gid = lane >> 2, tig = lane & 3;
#pragma unroll
    for (int mf = 0; mf < 2; mf++) {
        const int m0 = bm + wm * 32 + mf * 16 + gid;
#pragma unroll
        for (int nf = 0; nf < 8; nf++) {
            const int col = bn + wn * 64 + nf * 8 + tig * 2;
            const float b0 = __ldg(bias + col), b1 = __ldg(bias + col + 1);
            const float v00 = acc[mf][nf][0] + b0, v01 = acc[mf][nf][1] + b1;
            const float v10 = acc[mf][nf][2] + b0, v11 = acc[mf][nf][3] + b1;
            if (mode == MODE_HSPLIT) {
                const int h = col >> 6, d = col & 63;
                const int b_ = m0 >> 11, l0 = m0 & 2047;
                const size_t o0 = (((size_t)b_ * NH + h) * L_SEQ + l0) * HD + d;
                const size_t o1 = o0 + (size_t)8 * HD;
                *(__half2*)(Cf + o0) = __floats2half2_rn(v00, v01);
                *(__half2*)(Cf + o1) = __floats2half2_rn(v10, v11);
            } else {
                *(float2*)(C + (size_t)m0 * N + col) = make_float2(v00, v01);
                *(float2*)(C + (size_t)(m0 + 8) * N + col) = make_float2(v10, v11);
            }
        }
    }
}

// =====================================================================
// Dedicated qrel GEMM, grid (512 row-blocks, 3 tile-groups of 3).
// A smem-resident + reg fragments; B double-buffered; coalesced epilogue
// via padded smem staging. Copy-out bounded to row pitch QRP (tile 8
// covers cols 1024..1151 but only 1024..1055 are in-row).
// =====================================================================
#define QR_SMEM (16384 + 32768 + 34816 + 1024)
__global__ void __launch_bounds__(256) qrel_gemm()
{
    extern __shared__ char smc[];
    const uint32_t sb0 = smem_u32(smc);
    const uint32_t sbuf = (sb0 + 1023u) & ~1023u;
    const uint32_t uA = sbuf, uB = sbuf + 16384u, uS = sbuf + 49152u;

    const int tid = threadIdx.x;
    const int wid = tid >> 5, lane = tid & 31;
    const int wm = wid & 3, wn = wid >> 2;
    const int bm = blockIdx.x << 7;
    const int T0 = blockIdx.y * 3;
    const int gid = lane >> 2, tig = lane & 3;

    auto issue_b = [&](int t) {
        const uint32_t dst = uB + (uint32_t)(t & 1) * 16384u;
#pragma unroll
        for (int q = 0; q < 4; q++) {
            const int u = tid + (q << 8);
            const int r = u >> 3, i = u & 7;
            const int nr = t * 128 + r;
            cpasync16(dst + swz((uint32_t)(r * 128 + i * 16)),
                      (const uint4*)g_Ef + (size_t)nr * 8 + i, (nr < NEMB) ? 16u : 0u);
        }
        cp_commit();
    };

#pragma unroll
    for (int q = 0; q < 4; q++) {
        const int u = tid + (q << 8);
        const int r = u >> 3, i = u & 7;
        cpasync16(uA + swz((uint32_t)(r * 128 + i * 16)),
                  (const uint4*)g_Qf + (size_t)(bm + r) * 8 + i, 16u);
    }
    issue_b(T0);       // commits A+B0
    issue_b(T0 + 1);

    uint32_t a4[2][4][4];

    for (int tt = 0; tt < 3; tt++) {
        const int t = T0 + tt;
        if (tt < 2) {
            asm volatile("cp.async.wait_group 1;" ::: "memory");
        } else {
            asm volatile("cp.async.wait_group 0;" ::: "memory");
        }
        __syncthreads();

        if (tt == 0) {
#pragma unroll
            for (int kk = 0; kk < 4; kk++) {
                const uint32_t kb = (uint32_t)(kk << 5);
#pragma unroll
                for (int mf = 0; mf < 2; mf++) {
                    const uint32_t r = (uint32_t)(wm * 32 + mf * 16 + (lane & 15));
                    ldmx4(a4[mf][kk], uA + swz(r * 128 + kb + (uint32_t)((lane >> 4) << 4)));
                }
            }
        }

        const uint32_t uBt = uB + (uint32_t)(t & 1) * 16384u;
        float acc[2][8][4];
#pragma unroll
        for (int i = 0; i < 2; i++)
#pragma unroll
            for (int j = 0; j < 8; j++)
#pragma unroll
                for (int k = 0; k < 4; k++) acc[i][j][k] = 0.f;

#pragma unroll
        for (int kk = 0; kk < 4; kk++) {
            const uint32_t kb = (uint32_t)(kk << 5);
            uint32_t bh[16];
#pragma unroll
            for (int nf2 = 0; nf2 < 4; nf2++) {
                const uint32_t r = (uint32_t)(wn * 64 + nf2 * 16 + (lane & 7) + ((lane >> 4) << 3));
                ldmx4(bh + nf2 * 4, uBt + swz(r * 128 + kb + (uint32_t)(((lane >> 3) & 1) << 4)));
            }
#pragma unroll
            for (int mf = 0; mf < 2; mf++)
#pragma unroll
                for (int nf = 0; nf < 8; nf++)
                    mma_f16(acc[mf][nf], a4[mf][kk], bh + (nf >> 1) * 4 + (nf & 1) * 2);
        }
        __syncthreads();
        if (tt + 2 < 3) issue_b(t + 2);

        // stage tile in padded smem (272B pitch), then coalesced copy-out
#pragma unroll
        for (int mf = 0; mf < 2; mf++) {
            const int r0 = wm * 32 + mf * 16 + gid;
#pragma unroll
            for (int nf = 0; nf < 8; nf++) {
                const int col = wn * 64 + nf * 8 + tig * 2;
                *(__half2*)(smc + (uS - sb0) + r0 * 272 + col * 2) =
                    __floats2half2_rn(acc[mf][nf][0], acc[mf][nf][1]);
                *(__half2*)(smc + (uS - sb0) + (r0 + 8) * 272 + col * 2) =
                    __floats2half2_rn(acc[mf][nf][2], acc[mf][nf][3]);
            }
        }
        __syncthreads();
#pragma unroll
        for (int q = 0; q < 8; q++) {
            const int u = tid + (q << 8);
            const int r = u >> 4, i = u & 15;
            const int col = t * 128 + i * 8;
            if (col + 8 <= QRP) {   // BOUND: last tile writes only cols 1024..1055
                uint4 v = *(uint4*)(smc + (uS - sb0) + r * 272 + i * 16);
                *(uint4*)(g_qrel + (size_t)(bm + r) * QRP + col) = v;
            }
        }
        __syncthreads();
    }
}

// =====================================================================
// Flash attention, fp16 HMMA, register P, pipelined K/V, clip fast path.
// =====================================================================
#define FLASH_SMEM_BYTES 81920
#define NTILES (L_SEQ / 128)
__global__ void __launch_bounds__(256) flash_f16()
{
    extern __shared__ char smc[];
    const uint32_t sb = smem_u32(smc);
    const uint32_t uQ = sb;

    const int tid = threadIdx.x, w = tid >> 5, lane = tid & 31;
    const int tig = lane & 3, grp = lane >> 2;
    const int bh = blockIdx.y, i0 = blockIdx.x << 7;

    const uint4* gQ = (const uint4*)(g_Qf + (size_t)(bh * L_SEQ + i0) * HD);
    const uint4* gK = (const uint4*)(g_Kf + (size_t)bh * L_SEQ * HD);
    const uint4* gV = (const uint4*)(g_Vf + (size_t)bh * L_SEQ * HD);

    auto issue_kv = [&](int c) {
        const uint32_t uB = sb + 16384u + (uint32_t)(c & 1) * 32768u;
#pragma unroll
        for (int t = 0; t < 4; t++) {
            const int u = tid + (t << 8);
            const int r = u >> 3, i = u & 7;
            const uint32_t so = swz((uint32_t)(r * 128 + i * 16));
            const size_t gi = (size_t)(c * 128 + r) * 8 + i;
            cpasync16(uB + so, gK + gi, 16u);
            cpasync16(uB + 16384u + so, gV + gi, 16u);
        }
        cp_commit();
    };

#pragma unroll
    for (int t = 0; t < 4; t++) {
        const int u = tid + (t << 8);
        const int r = u >> 3, i = u & 7;
        cpasync16(uQ + swz((uint32_t)(r * 128 + i * 16)), gQ + r * 8 + i, 16u);
    }
    issue_kv(0);
    issue_kv(1);

    float O[8][4];
#pragma unroll
    for (int i = 0; i < 8; i++)
#pragma unroll
        for (int j = 0; j < 4; j++) O[i][j] = 0.f;
    float m_a = -1e30f, m_b = -1e30f, l_a = 0.f, l_b = 0.f;

    const int ia = i0 + w * 16 + grp, ib = ia + 8;
    const __half* qra = g_qrel + (size_t)(bh * L_SEQ + ia) * QRP + 512;
    const __half* qrb = g_qrel + (size_t)(bh * L_SEQ + ib) * QRP + 512;
    const float eaLo = __half2float(__ldg(qra - 512)), eaHi = __half2float(__ldg(qra + 512));
    const float ebLo = __half2float(__ldg(qrb - 512)), ebHi = __half2float(__ldg(qrb + 512));

    const float SCL = 0.125f * 1.4426950408889634f;

    for (int c = 0; c < NTILES; c++) {
        const int j0 = c << 7;
        if (c + 1 < NTILES) {
            asm volatile("cp.async.wait_group 1;" ::: "memory");
        } else {
            asm volatile("cp.async.wait_group 0;" ::: "memory");
        }
        __syncthreads();
        const uint32_t uK = sb + 16384u + (uint32_t)(c & 1) * 32768u;
        const uint32_t uV = uK + 16384u;

        float s[16][4];
#pragma unroll
        for (int i = 0; i < 16; i++)
#pragma unroll
            for (int j = 0; j < 4; j++) s[i][j] = 0.f;

        const uint32_t ra = (uint32_t)(w * 16 + (lane & 15));
#pragma unroll
        for (int kk = 0; kk < 4; kk++) {
            const uint32_t kb = (uint32_t)(kk << 5);
            uint32_t q4[4];
            ldmx4(q4, uQ + swz(ra * 128 + kb + (uint32_t)((lane >> 4) << 4)));
#pragma unroll
            for (int g = 0; g < 8; g++) {
                const uint32_t rb = (uint32_t)(g * 16 + (lane & 7) + ((lane >> 4) << 3));
                uint32_t k4[4];
                ldmx4(k4, uK + swz(rb * 128 + kb + (uint32_t)(((lane >> 3) & 1) << 4)));
                mma_f16(s[2 * g],     q4, k4);
                mma_f16(s[2 * g + 1], q4, k4 + 2);
            }
        }

        // ---- positional term: constant fast path for fully-clipped rows ----
        const bool cA = (j0 >= ia + 512) || (j0 + 127 <= ia - 512);
        const bool cB = (j0 >= ib + 512) || (j0 + 127 <= ib - 512);
        const float addA = (j0 >= ia + 512) ? eaHi : eaLo;
        const float addB = (j0 >= ib + 512) ? ebHi : ebLo;
#pragma unroll
        for (int nf = 0; nf < 16; nf++) {
            const int j = j0 + nf * 8 + tig * 2;
            if (cA) {
                s[nf][0] = (s[nf][0] + addA) * SCL;
                s[nf][1] = (s[nf][1] + addA) * SCL;
            } else {
                const int e0a = min(max(j - ia, -512), 512);
                const int e1a = min(max(j + 1 - ia, -512), 512);
                s[nf][0] = (s[nf][0] + __half2float(__ldg(qra + e0a))) * SCL;
                s[nf][1] = (s[nf][1] + __half2float(__ldg(qra + e1a))) * SCL;
            }
            if (cB) {
                s[nf][2] = (s[nf][2] + addB) * SCL;
                s[nf][3] = (s[nf][3] + addB) * SCL;
            } else {
                const int e0b = min(max(j - ib, -512), 512);
                const int e1b = min(max(j + 1 - ib, -512), 512);
                s[nf][2] = (s[nf][2] + __half2float(__ldg(qrb + e0b))) * SCL;
                s[nf][3] = (s[nf][3] + __half2float(__ldg(qrb + e1b))) * SCL;
            }
        }

        float ma = -1e30f, mb = -1e30f;
#pragma unroll
        for (int nf = 0; nf < 16; nf++) {
            ma = fmaxf(ma, fmaxf(s[nf][0], s[nf][1]));
            mb = fmaxf(mb, fmaxf(s[nf][2], s[nf][3]));
        }
        ma = fmaxf(ma, __shfl_xor_sync(0xffffffffu, ma, 1));
        ma = fmaxf(ma, __shfl_xor_sync(0xffffffffu, ma, 2));
        mb = fmaxf(mb, __shfl_xor_sync(0xffffffffu, mb, 1));
        mb = fmaxf(mb, __shfl_xor_sync(0xffffffffu, mb, 2));
        const float mna = fmaxf(m_a, ma), mnb = fmaxf(m_b, mb);
        const float ca = exp2f(m_a - mna), cb = exp2f(m_b - mnb);
        m_a = mna; m_b = mnb;

        uint32_t pA[16], pB[16];
        float sa = 0.f, sb2 = 0.f;
#pragma unroll
        for (int nf = 0; nf < 16; nf++) {
            const float p0 = exp2f(s[nf][0] - m_a);
            const float p1 = exp2f(s[nf][1] - m_a);
            const float p2 = exp2f(s[nf][2] - m_b);
            const float p3 = exp2f(s[nf][3] - m_b);
            sa += p0 + p1;
            sb2 += p2 + p3;
            pA[nf] = packh2(p0, p1);
            pB[nf] = packh2(p2, p3);
        }
        sa += __shfl_xor_sync(0xffffffffu, sa, 1);
        sa += __shfl_xor_sync(0xffffffffu, sa, 2);
        sb2 += __shfl_xor_sync(0xffffffffu, sb2, 1);
        sb2 += __shfl_xor_sync(0xffffffffu, sb2, 2);
        l_a = l_a * ca + sa;
        l_b = l_b * cb + sb2;
#pragma unroll
        for (int nf2 = 0; nf2 < 8; nf2++) {
            O[nf2][0] *= ca; O[nf2][1] *= ca;
            O[nf2][2] *= cb; O[nf2][3] *= cb;
        }

#pragma unroll
        for (int k = 0; k < 8; k++) {
            uint32_t a4[4] = { pA[2 * k], pB[2 * k], pA[2 * k + 1], pB[2 * k + 1] };
#pragma unroll
            for (int g = 0; g < 4; g++) {
                const uint32_t rv = (uint32_t)(k * 16 + (lane & 7) + (((lane >> 3) & 1) << 3));
                uint32_t v4[4];
                ldmx4t(v4, uV + swz(rv * 128 + (uint32_t)(g * 32) + (uint32_t)((lane >> 4) << 4)));
                mma_f16(O[2 * g],     a4, v4);
                mma_f16(O[2 * g + 1], a4, v4 + 2);
            }
        }
        __syncthreads();
        if (c + 2 < NTILES) issue_kv(c + 2);
    }

    const float inva = 1.f / l_a, invb = 1.f / l_b;
    const int b_ = bh >> 4, h = bh & 15;
    const size_t rowa = (size_t)b_ * L_SEQ + (i0 + w * 16 + grp);
    const size_t rowb = rowa + 8;
#pragma unroll
    for (int nf2 = 0; nf2 < 8; nf2++) {
        const int col = h * 64 + nf2 * 8 + tig * 2;
        *(__half2*)(g_Act + rowa * DM + col) = __floats2half2_rn(O[nf2][0] * inva, O[nf2][1] * inva);
        *(__half2*)(g_Act + rowb * DM + col) = __floats2half2_rn(O[nf2][2] * invb, O[nf2][3] * invb);
    }
}

// =====================================================================
extern "C" void kernel_launch(void* const* d_in, const int* in_sizes, int n_in,
                              void* d_out, int out_size)
{
    const float* query = (const float*)d_in[0];
    const float* key   = (const float*)d_in[1];
    const float* value = (const float*)d_in[2];
    const float* wq    = (const float*)d_in[3];
    const float* bq    = (const float*)d_in[4];
    const float* wk    = (const float*)d_in[5];
    const float* bk    = (const float*)d_in[6];
    const float* wv    = (const float*)d_in[7];
    const float* bv    = (const float*)d_in[8];
    const float* wo    = (const float*)d_in[9];
    const float* bo    = (const float*)d_in[10];
    const float* rel   = (const float*)d_in[11];

    __half *pQf, *pKf, *pVf, *pAct, *pWh;
    cudaGetSymbolAddress((void**)&pQf, g_Qf);
    cudaGetSymbolAddress((void**)&pKf, g_Kf);
    cudaGetSymbolAddress((void**)&pVf, g_Vf);
    cudaGetSymbolAddress((void**)&pAct, g_Act);
    cudaGetSymbolAddress((void**)&pWh, g_Wh);

    static cudaStream_t s1 = nullptr;
    static cudaEvent_t evFork = nullptr, evKV = nullptr;
    static bool attrDone = false;
    if (!s1) {
        cudaStreamCreateWithFlags(&s1, cudaStreamNonBlocking);
        cudaEventCreateWithFlags(&evFork, cudaEventDisableTiming);
        cudaEventCreateWithFlags(&evKV, cudaEventDisableTiming);
    }
    const int GEMM_SMEM = 2 * 32768 + 1024;
    if (!attrDone) {
        cudaFuncSetAttribute(hmma_gemm2, cudaFuncAttributeMaxDynamicSharedMemorySize, GEMM_SMEM);
        cudaFuncSetAttribute(qrel_gemm, cudaFuncAttributeMaxDynamicSharedMemorySize, QR_SMEM);
        cudaFuncSetAttribute(flash_f16, cudaFuncAttributeMaxDynamicSharedMemorySize, FLASH_SMEM_BYTES);
        attrDone = true;
    }

    // ---- shared preprocessing on main stream ----
    transpose4<<<dim3(32, 32, 4), dim3(32, 32)>>>(wq, wk, wv, wo);
    convert4_f16<<<dim3(4096, 4), 256>>>(query, key, value, rel);
    cudaEventRecord(evFork, 0);
    cudaStreamWaitEvent(s1, evFork, 0);

    // ---- main stream: Q projection, then qrel ----
    GemmBatch qb;
    qb.A[0] = pAct;   qb.A[1] = pAct;   qb.A[2] = pAct;
    qb.bias[0] = bq;  qb.bias[1] = bq;  qb.bias[2] = bq;
    qb.Cf[0] = pQf;   qb.Cf[1] = pQf;   qb.Cf[2] = pQf;
    hmma_gemm2<<<dim3(8, 32, 1), 256, GEMM_SMEM>>>(qb, pWh, nullptr,
                                                   MROWS, DM, DM, MODE_HSPLIT);
    qrel_gemm<<<dim3(512, 3), 256, QR_SMEM>>>();

    // ---- side stream: K and V projections ----
    GemmBatch kvb;
    kvb.A[0] = pAct + NELEM;  kvb.A[1] = pAct + 2 * NELEM;  kvb.A[2] = pAct;
    kvb.bias[0] = bk;         kvb.bias[1] = bv;             kvb.bias[2] = bk;
    kvb.Cf[0] = pKf;          kvb.Cf[1] = pVf;              kvb.Cf[2] = pKf;
    hmma_gemm2<<<dim3(8, 32, 2), 256, GEMM_SMEM, s1>>>(kvb, pWh + (size_t)DM * DM, nullptr,
                                                       MROWS, DM, DM, MODE_HSPLIT);
    cudaEventRecord(evKV, s1);
    cudaStreamWaitEvent(0, evKV, 0);

    // ---- attention -> g_Act slot 0 ----
    flash_f16<<<dim3(16, 32), 256, FLASH_SMEM_BYTES>>>();

    // ---- output projection ----
    GemmBatch op;
    op.A[0] = pAct; op.A[1] = pAct; op.A[2] = pAct;
    op.bias[0] = bo; op.bias[1] = bo; op.bias[2] = bo;
    op.Cf[0] = nullptr; op.Cf[1] = nullptr; op.Cf[2] = nullptr;
    hmma_gemm2<<<dim3(8, 32, 1), 256, GEMM_SMEM>>>(op, pWh + (size_t)3 * DM * DM,
                                                   (float*)d_out, MROWS, DM, DM, MODE_PLAIN);
}